// round 10
// baseline (speedup 1.0000x reference)
#include <cuda_runtime.h>
#include <cstdint>

#define SL   3264            // seq length L
#define KK   12
#define LPK  (SL / KK)       // 272
#define SS   8               // streams
#define BB   64              // batch
#define AA   4               // antennas
#define RR   (SL / 4)        // 816 (L / LOCC)
#define NOFF 21              // delay candidates -10..10
#define TILE 256             // l-tile for k_final
#define NTILE 13             // ceil(3264/256)
#define PDIM 816             // decimated length L/4

#define SMEM_DYN (AA * 2 * SL * 4)   // 104448 B: 4 antennas x (re,im) x 3264 f32

// ---- scratch (device-global: allocation-free contract) ----
__device__ int    g_m[SS * BB];                   // (t_off + ideal_peak) mod L
__device__ int    g_tt[SS * BB];                  // t_off mod L
__device__ float2 g_havg[SS * BB * AA * RR];      // OCC-averaged channel, 13.4 MB

// ---- packed f32x2 helpers (sm_103a dual-lane fp32) ----
#define F2MUL(o, a, b)    asm("mul.rn.f32x2 %0, %1, %2;"      : "=l"(o) : "l"(a), "l"(b))
#define F2FMA(o, a, b, c) asm("fma.rn.f32x2 %0, %1, %2, %3;"  : "=l"(o) : "l"(a), "l"(b), "l"(c))
#define F2ADD(o, a, b)    asm("add.rn.f32x2 %0, %1, %2;"      : "=l"(o) : "l"(a), "l"(b))
#define SGNMASK 0x8000000080000000ULL

static __device__ __forceinline__ uint64_t pk2(float lo, float hi) {
    uint64_t r; asm("mov.b64 %0, {%1, %2};" : "=l"(r) : "f"(lo), "f"(hi)); return r;
}
static __device__ __forceinline__ float lo2(uint64_t v) {
    float a, b; asm("mov.b64 {%0, %1}, %2;" : "=f"(a), "=f"(b) : "l"(v)); return a;
}
static __device__ __forceinline__ float hi2(uint64_t v) {
    float a, b; asm("mov.b64 {%0, %1}, %2;" : "=f"(a), "=f"(b) : "l"(v)); return b;
}
static __device__ __forceinline__ uint64_t splat(float v) { return pk2(v, v); }

// fp32 2*pi/L, matching reference fp32 angle math
#define WF ((float)(6.283185307179586476925286766559 / 3264.0))

// fast phasor: e^{i th k}; reduce to (-pi, pi] for MUFU accuracy
static __device__ __forceinline__ float2 phasor(int k) {
    if (k > SL / 2) k -= SL;
    float s, c;
    __sincosf(WF * (float)k, &s, &c);
    return make_float2(c, s);
}

static __device__ __forceinline__ int modL(int x) { x %= SL; return x < 0 ? x + SL : x; }

// packed complex in-place multiply: (ar,ai) *= (br,bi)
#define CMUL(ar, ai, br, bi) do {            \
    uint64_t _m, _nr;                        \
    F2MUL(_m, ai, bi); _m ^= SGNMASK;        \
    F2FMA(_nr, ar, br, _m);                  \
    F2MUL(_m, ai, br);                       \
    F2FMA(ai, ar, bi, _m);                   \
    ar = _nr;                                \
} while (0)

// ---- mbarrier / TMA-bulk helpers ----
static __device__ __forceinline__ uint32_t smem_u32(const void* p) {
    uint32_t r;
    asm("{ .reg .u64 t; cvta.to.shared.u64 t, %1; cvt.u32.u64 %0, t; }" : "=r"(r) : "l"(p));
    return r;
}
#define MBAR_INIT(addr, cnt) \
    asm volatile("mbarrier.init.shared.b64 [%0], %1;" :: "r"(addr), "r"(cnt) : "memory")
#define MBAR_EXPECT_TX(addr, bytes) \
    asm volatile("mbarrier.arrive.expect_tx.shared.b64 _, [%0], %1;" :: "r"(addr), "r"(bytes) : "memory")
#define TMA_BULK_G2S(dst, src, bytes, mbar) \
    asm volatile("cp.async.bulk.shared::cta.global.mbarrier::complete_tx::bytes [%0], [%1], %2, [%3];" \
        :: "r"(dst), "l"(src), "r"(bytes), "r"(mbar) : "memory")
static __device__ __forceinline__ void mbar_wait0(uint32_t addr) {
    asm volatile(
        "{\n\t"
        ".reg .pred P;\n\t"
        "WAIT_%=:\n\t"
        "mbarrier.try_wait.parity.acquire.cta.shared::cta.b64 P, [%0], 0, 0x989680;\n\t"
        "@P bra.uni DONE_%=;\n\t"
        "bra.uni WAIT_%=;\n\t"
        "DONE_%=:\n\t"
        "}" :: "r"(addr) : "memory");
}

// ---------------------------------------------------------------------------
// Chebyshev accumulation chunk for one class: given W (FFT4 output), seed s,
// phi = e^{i 4 th p}, tc = 2 Re(phi): acc_j += (+-) W*s*phi^j  (3-term chain,
// alternating-sign substitution; signs consistent per j; only |acc|^2 used).
// ---------------------------------------------------------------------------
template <int S>
static __device__ __forceinline__ void eval_cheb(
    uint64_t Wr, uint64_t Wi, uint64_t sr, uint64_t si,
    uint64_t phir, uint64_t phii, uint64_t tc, uint64_t ntc,
    uint64_t* accr, uint64_t* acci)
{
    uint64_t m, v0r, v0i;
    F2MUL(m, Wi, si); m ^= SGNMASK;
    F2FMA(v0r, Wr, sr, m);
    F2MUL(m, Wi, sr);
    F2FMA(v0i, Wr, si, m);
    F2ADD(accr[0], accr[0], v0r);
    F2ADD(acci[0], acci[0], v0i);

    uint64_t v1r, v1i;
    F2MUL(m, v0i, phii); m ^= SGNMASK;
    F2FMA(v1r, v0r, phir, m);
    F2MUL(m, v0i, phir);
    F2FMA(v1i, v0r, phii, m);
    F2ADD(accr[1], accr[1], v1r);
    F2ADD(acci[1], acci[1], v1i);

    uint64_t pr = v0r, pi_ = v0i, cr = v1r, ci_ = v1i;
#pragma unroll
    for (int j = 2; j < S; j++) {
        uint64_t co = (j & 1) ? tc : ntc;
        uint64_t nr, ni;
        F2FMA(nr, co, cr, pr);
        F2FMA(ni, co, ci_, pi_);
        pr = cr; pi_ = ci_; cr = nr; ci_ = ni;
        F2ADD(accr[j], accr[j], nr);
        F2ADD(acci[j], acci[j], ni);
    }
}

// warp-reduce packed complex, lane0 writes |X|^2
template <int S>
static __device__ __forceinline__ void reduce_pows(
    float* powdst /*stride-4*/, const uint64_t* accr, const uint64_t* acci, int lane)
{
#pragma unroll
    for (int j = 0; j < S; j++) {
        float rr = lo2(accr[j]) + hi2(accr[j]);
        float ii = lo2(acci[j]) + hi2(acci[j]);
#pragma unroll
        for (int o = 16; o > 0; o >>= 1) {
            rr += __shfl_xor_sync(0xFFFFFFFFu, rr, o);
            ii += __shfl_xor_sync(0xFFFFFFFFu, ii, o);
        }
        if (lane == 0) powdst[4 * j] = rr * rr + ii * ii;
    }
}

// ---------------------------------------------------------------------------
// Two residue classes per warp (sharing data loads + FFT4 halves).
//   PARITY 0: class0 (S=5, dmin=-8, slot+2) and class2 (S=6, dmin=-10, slot+0)
//   PARITY 1: class1 (S=5, dmin=-7, slot+3) and class3 (S=5, dmin=-9, slot+1)
// ---------------------------------------------------------------------------
template <int PARITY>
static __device__ __forceinline__ void do_class2(
    const float* br, const float* bi,   // smem, 3264 floats each
    int n0, int lane, float* powrow)
{
    constexpr int SA   = 5;
    constexpr int SB   = (PARITY == 0) ? 6 : 5;
    constexpr int DMA  = (PARITY == 0) ? -8  : -7;
    constexpr int DMB  = (PARITY == 0) ? -10 : -9;
    constexpr int OFFA = DMA + 10;   // 2 or 3
    constexpr int OFFB = DMB + 10;   // 0 or 1

    const int p0 = 2 * lane;     // packed pair (p0, p0+1); stride 64/iter
    const int fA = n0 + DMA;
    const int fB = n0 + DMB;

    float2 ea = phasor(modL(fA * p0)), eb = phasor(modL(fA * (p0 + 1)));
    uint64_t sAr = pk2(ea.x, eb.x), sAi = pk2(ea.y, eb.y);
    ea = phasor(modL(fB * p0)); eb = phasor(modL(fB * (p0 + 1)));
    uint64_t sBr = pk2(ea.x, eb.x), sBi = pk2(ea.y, eb.y);

    float2 st = phasor(modL(fA * 64));
    uint64_t stAr = splat(st.x), stAi = splat(st.y);
    st = phasor(modL(fB * 64));
    uint64_t stBr = splat(st.x), stBi = splat(st.y);

    float2 pa = phasor(4 * p0), pb = phasor(4 * p0 + 4);
    uint64_t phir = pk2(pa.x, pb.x), phii = pk2(pa.y, pb.y);
    float2 psc = phasor(256);
    uint64_t pstr = splat(psc.x), psti = splat(psc.y);

    uint64_t aAr[SA], aAi[SA], aBr[SB], aBi[SB];
#pragma unroll
    for (int j = 0; j < SA; j++) { aAr[j] = aAi[j] = 0ULL; }
#pragma unroll
    for (int j = 0; j < SB; j++) { aBr[j] = aBi[j] = 0ULL; }

    int p = p0;
#pragma unroll 1
    for (int it = 0; it < 13; ++it, p += 64) {
        const bool v = (p < PDIM);
        uint64_t xr0 = v ? *(const uint64_t*)(br + p)            : 0ULL;
        uint64_t xr1 = v ? *(const uint64_t*)(br + p + PDIM)     : 0ULL;
        uint64_t xr2 = v ? *(const uint64_t*)(br + p + 2 * PDIM) : 0ULL;
        uint64_t xr3 = v ? *(const uint64_t*)(br + p + 3 * PDIM) : 0ULL;
        uint64_t xi0 = v ? *(const uint64_t*)(bi + p)            : 0ULL;
        uint64_t xi1 = v ? *(const uint64_t*)(bi + p + PDIM)     : 0ULL;
        uint64_t xi2 = v ? *(const uint64_t*)(bi + p + 2 * PDIM) : 0ULL;
        uint64_t xi3 = v ? *(const uint64_t*)(bi + p + 3 * PDIM) : 0ULL;

        uint64_t WAr, WAi, WBr, WBi;
        if (PARITY == 0) {
            // even FFT4 outputs: t0 = z0+z2, t2 = z1+z3; W0 = t0+t2, W2 = t0-t2
            uint64_t t0r, t0i, t2r, t2i;
            F2ADD(t0r, xr0, xr2); F2ADD(t0i, xi0, xi2);
            F2ADD(t2r, xr1, xr3); F2ADD(t2i, xi1, xi3);
            F2ADD(WAr, t0r, t2r); F2ADD(WAi, t0i, t2i);
            uint64_t n1 = t2r ^ SGNMASK, n2 = t2i ^ SGNMASK;
            F2ADD(WBr, t0r, n1);  F2ADD(WBi, t0i, n2);
        } else {
            // odd: t1 = z0-z2, t3 = z1-z3; W1 = t1 + i t3, W3 = t1 - i t3
            uint64_t nr2 = xr2 ^ SGNMASK, ni2 = xi2 ^ SGNMASK;
            uint64_t nr3 = xr3 ^ SGNMASK, ni3 = xi3 ^ SGNMASK;
            uint64_t t1r, t1i, t3r, t3i;
            F2ADD(t1r, xr0, nr2); F2ADD(t1i, xi0, ni2);
            F2ADD(t3r, xr1, nr3); F2ADD(t3i, xi1, ni3);
            uint64_t nt3i = t3i ^ SGNMASK, nt3r = t3r ^ SGNMASK;
            F2ADD(WAr, t1r, nt3i); F2ADD(WAi, t1i, t3r);
            F2ADD(WBr, t1r, t3i);  F2ADD(WBi, t1i, nt3r);
        }

        uint64_t tc, ntc;
        F2ADD(tc, phir, phir);
        ntc = tc ^ SGNMASK;

        eval_cheb<SA>(WAr, WAi, sAr, sAi, phir, phii, tc, ntc, aAr, aAi);
        eval_cheb<SB>(WBr, WBi, sBr, sBi, phir, phii, tc, ntc, aBr, aBi);

        CMUL(sAr, sAi, stAr, stAi);
        CMUL(sBr, sBi, stBr, stBi);
        CMUL(phir, phii, pstr, psti);
    }

    reduce_pows<SA>(powrow + OFFA, aAr, aAi, lane);
    reduce_pows<SB>(powrow + OFFB, aBr, aBi, lane);
}

// ---------------------------------------------------------------------------
// k_main: TMA-bulk the whole (s,b) slice into smem, then phase A (timing
//   search, 2 classes/warp) + argmax + phase B (OCC avg), all smem-fed.
//   One block per (s,b); 256 threads = 8 warps: warp w -> antenna w>>1,
//   parity w&1.
// ---------------------------------------------------------------------------
__global__ void __launch_bounds__(256)
k_main(const float* __restrict__ lsr, const float* __restrict__ lsi,
       const int* __restrict__ cs) {
    extern __shared__ float smbuf[];          // [(a*2+c) * SL], 104448 B
    __shared__ uint64_t mbar[AA];
    __shared__ float    spow[AA][NOFF];
    __shared__ float    shpow[NOFF];
    __shared__ int      sh_mm;

    const int sb   = blockIdx.x;
    const int s    = sb / BB;
    const int w    = threadIdx.x >> 5;
    const int lane = threadIdx.x & 31;

    const int ideal = ((KK - cs[s]) % KK) * LPK;   // in [0,SL), multiple of 4

    if (threadIdx.x == 0) {
#pragma unroll
        for (int a = 0; a < AA; a++) MBAR_INIT(smem_u32(&mbar[a]), 1);
    }
    __syncthreads();
    if (threadIdx.x == 0) {
#pragma unroll
        for (int a = 0; a < AA; a++) {
            uint32_t mb = smem_u32(&mbar[a]);
            MBAR_EXPECT_TX(mb, 2 * SL * 4);
            const float* srcr = lsr + ((size_t)sb * AA + a) * SL;
            const float* srci = lsi + ((size_t)sb * AA + a) * SL;
            TMA_BULK_G2S(smem_u32(smbuf + (a * 2) * SL),     srcr, SL * 4, mb);
            TMA_BULK_G2S(smem_u32(smbuf + (a * 2 + 1) * SL), srci, SL * 4, mb);
        }
    }

    // ---- phase A: one double-class job per warp ----
    const int a      = w >> 1;
    const int parity = w & 1;
    mbar_wait0(smem_u32(&mbar[a]));
    {
        const float* br = smbuf + (a * 2) * SL;
        const float* bi = smbuf + (a * 2 + 1) * SL;
        if (parity == 0) do_class2<0>(br, bi, ideal, lane, &spow[a][0]);
        else             do_class2<1>(br, bi, ideal, lane, &spow[a][0]);
    }
    __syncthreads();

    // ---- argmax over candidates (first-max tie rule) ----
    if (threadIdx.x < NOFF) {
        int d = threadIdx.x;
        shpow[d] = spow[0][d] + spow[1][d] + spow[2][d] + spow[3][d];
    }
    __syncthreads();
    if (threadIdx.x == 0) {
        int   best = 0;
        float bp   = shpow[0];
        for (int j = 1; j < NOFF; j++)
            if (shpow[j] > bp) { bp = shpow[j]; best = j; }
        int toff = best - 10;
        int mmv  = modL(toff + ideal);
        g_m[sb]  = mmv;
        g_tt[sb] = modL(toff);
        sh_mm    = mmv;
    }
    __syncthreads();

    // ---- phase B: OCC averaging from SMEM ----
    const int mmv = sh_mm;
    float2 msv = phasor(mmv);                        // e^{i th mm}
    float2 spv = phasor((mmv * 1024) % SL);          // r += 256 step
    float2 sd0 = phasor((mmv * 4 * (int)threadIdx.x) % SL);

#pragma unroll
    for (int aa = 0; aa < AA; aa++) {
        const float* br2 = smbuf + (aa * 2) * SL;
        const float* bi2 = smbuf + (aa * 2 + 1) * SL;
        float2* ho = g_havg + ((size_t)sb * AA + aa) * RR;
        float pc = sd0.x, ps = sd0.y;
        for (int r = threadIdx.x; r < RR; r += 256) {
            int l0 = 4 * r;
            float4 xr = *(const float4*)(br2 + l0);
            float4 xi = *(const float4*)(bi2 + l0);
            float xrv[4] = {xr.x, xr.y, xr.z, xr.w};
            float xiv[4] = {xi.x, xi.y, xi.z, xi.w};
            float qc = pc, qs = ps;
            float sr = 0.0f, si = 0.0f;
#pragma unroll
            for (int j = 0; j < 4; j++) {
                sr += xrv[j] * qc - xiv[j] * qs;
                si += xrv[j] * qs + xiv[j] * qc;
                if (j < 3) {
                    float nc = qc * msv.x - qs * msv.y;
                    float ns = qc * msv.y + qs * msv.x;
                    qc = nc; qs = ns;
                }
            }
            ho[r] = make_float2(sr * 0.25f, si * 0.25f);
            float nc = pc * spv.x - ps * spv.y;
            float ns = pc * spv.y + ps * spv.x;
            pc = nc; ps = ns;
        }
    }
}

// ---------------------------------------------------------------------------
// k_final: warp-per-stream over a 256-l tile for one (b,a); 8 l's per thread.
// ---------------------------------------------------------------------------
__global__ void __launch_bounds__(256)
k_final(const float* __restrict__ lsr, const float* __restrict__ lsi,
        float* __restrict__ out) {
    const int blk  = blockIdx.x;
    const int ba   = blk / NTILE;
    const int tile = blk % NTILE;
    const int a    = ba % AA;
    const int b    = ba / AA;
    const int s    = threadIdx.x >> 5;   // warp = stream
    const int lane = threadIdx.x & 31;

    const int lbase = tile * TILE;
    const int l0    = lbase + lane * 8;
    const bool act  = (l0 < SL);

    __shared__ float shc[SS][2 * TILE];   // recon contributions (16 KB)
    __shared__ float shres[2 * TILE];     // residual

    const int sb = s * BB + b;
    const int mm = g_m[sb];
    const int tt = g_tt[sb];
    const float2* hv = g_havg + ((size_t)sb * AA + a) * RR;

    float hr[8], hi[8], pr[8], pi[8];

    if (act) {
        int g = l0 >> 2;                       // groups g (j=0..3), g+1 (j=4..7)
        float2 hm = hv[max(g - 1, 0)];
        float2 h0 = hv[g];
        float2 h1 = hv[g + 1];                 // g+1 <= RR-1 always
        float2 h2 = hv[min(g + 2, RR - 1)];

        // interp: within-group jj: 0,1 -> (lo,hi) f=.625,.875 ; 2,3 -> f=.125,.375
        hr[0] = hm.x * 0.375f + h0.x * 0.625f;  hi[0] = hm.y * 0.375f + h0.y * 0.625f;
        hr[1] = hm.x * 0.125f + h0.x * 0.875f;  hi[1] = hm.y * 0.125f + h0.y * 0.875f;
        hr[2] = h0.x * 0.875f + h1.x * 0.125f;  hi[2] = h0.y * 0.875f + h1.y * 0.125f;
        hr[3] = h0.x * 0.625f + h1.x * 0.375f;  hi[3] = h0.y * 0.625f + h1.y * 0.375f;
        hr[4] = h0.x * 0.375f + h1.x * 0.625f;  hi[4] = h0.y * 0.375f + h1.y * 0.625f;
        hr[5] = h0.x * 0.125f + h1.x * 0.875f;  hi[5] = h0.y * 0.125f + h1.y * 0.875f;
        hr[6] = h1.x * 0.875f + h2.x * 0.125f;  hi[6] = h1.y * 0.875f + h2.y * 0.125f;
        hr[7] = h1.x * 0.625f + h2.x * 0.375f;  hi[7] = h1.y * 0.625f + h2.y * 0.375f;

        // mm*l0 <= 3263*3256: int32-safe
        float2 pm = phasor((mm * l0) % SL);
        float2 ms = phasor(mm);
        float pmc = pm.x, pms = pm.y;

        float cr[8], cc[8];
#pragma unroll
        for (int j = 0; j < 8; j++) {
            pr[j] = pmc; pi[j] = pms;
            cr[j] = hr[j] * pmc + hi[j] * pms;   // h_interp * conj(ph_m)
            cc[j] = hi[j] * pmc - hr[j] * pms;
            if (j < 7) {
                float nc = pmc * ms.x - pms * ms.y;
                float ns = pmc * ms.y + pms * ms.x;
                pmc = nc; pms = ns;
            }
        }
        float4* dst = (float4*)&shc[s][lane * 16];
        dst[0] = make_float4(cr[0], cc[0], cr[1], cc[1]);
        dst[1] = make_float4(cr[2], cc[2], cr[3], cc[3]);
        dst[2] = make_float4(cr[4], cc[4], cr[5], cc[5]);
        dst[3] = make_float4(cr[6], cc[6], cr[7], cc[7]);
    }
    __syncthreads();

    // residual: thread t handles both components of tile-local l = t
    {
        int ll = threadIdx.x;
        int lg = lbase + ll;
        if (lg < SL) {
            float sumr = 0.0f, sumi = 0.0f;
#pragma unroll
            for (int ss2 = 0; ss2 < SS; ss2++) {
                sumr += shc[ss2][ll * 2];
                sumi += shc[ss2][ll * 2 + 1];
            }
            shres[ll * 2]     = lsr[(size_t)ba * SL + lg] - sumr;
            shres[ll * 2 + 1] = lsi[(size_t)ba * SL + lg] - sumi;
        }
    }
    __syncthreads();

    if (act) {
        float2 pt = phasor((tt * l0) % SL);
        float2 ts = phasor(tt);
        float ptc = pt.x, pts = pt.y;

        float4 rq[4];
        rq[0] = *(float4*)&shres[lane * 16];
        rq[1] = *(float4*)&shres[lane * 16 + 4];
        rq[2] = *(float4*)&shres[lane * 16 + 8];
        rq[3] = *(float4*)&shres[lane * 16 + 12];
        const float* rf = (const float*)rq;

        float outr[8], outi[8];
#pragma unroll
        for (int j = 0; j < 8; j++) {
            float rre = rf[2 * j], rim = rf[2 * j + 1];
            // w = h_interp + residual * ph_m
            float wr = hr[j] + rre * pr[j] - rim * pi[j];
            float wi = hi[j] + rre * pi[j] + rim * pr[j];
            // out = w * conj(ph_T)
            outr[j] = wr * ptc + wi * pts;
            outi[j] = wi * ptc - wr * pts;
            if (j < 7) {
                float nc = ptc * ts.x - pts * ts.y;
                float ns = ptc * ts.y + pts * ts.x;
                ptc = nc; pts = ns;
            }
        }

        const size_t TOT = (size_t)SS * BB * AA * SL;
        size_t off = ((size_t)sb * AA + a) * SL + (size_t)l0;
        *(float4*)(out + off)           = make_float4(outr[0], outr[1], outr[2], outr[3]);
        *(float4*)(out + off + 4)       = make_float4(outr[4], outr[5], outr[6], outr[7]);
        *(float4*)(out + TOT + off)     = make_float4(outi[0], outi[1], outi[2], outi[3]);
        *(float4*)(out + TOT + off + 4) = make_float4(outi[4], outi[5], outi[6], outi[7]);
    }
}

// ---------------------------------------------------------------------------
extern "C" void kernel_launch(void* const* d_in, const int* in_sizes, int n_in,
                              void* d_out, int out_size) {
    (void)in_sizes; (void)n_in; (void)out_size;
    const float* lsr = (const float*)d_in[0];
    const float* lsi = (const float*)d_in[1];
    const int*   cs  = (const int*)d_in[2];
    float*       out = (float*)d_out;

    cudaFuncSetAttribute(k_main, cudaFuncAttributeMaxDynamicSharedMemorySize, SMEM_DYN);

    k_main<<<SS * BB, 256, SMEM_DYN>>>(lsr, lsi, cs);
    k_final<<<BB * AA * NTILE, 256>>>(lsr, lsi, out);
}

// round 11
// speedup vs baseline: 1.1341x; 1.1341x over previous
#include <cuda_runtime.h>
#include <cstdint>

#define SL   3264            // seq length L
#define KK   12
#define LPK  (SL / KK)       // 272
#define SS   8               // streams
#define BB   64              // batch
#define AA   4               // antennas
#define RR   (SL / 4)        // 816 (L / LOCC)
#define NOFF 21              // delay candidates -10..10
#define TILE 128             // l-tile for k_final
#define NTILE 26             // ceil(3264/128)
#define PDIM 816             // decimated length L/4

#define SMEM_DYN (AA * 2 * SL * 4)   // 104448 B: 4 antennas x (re,im) x 3264 f32

// ---- scratch (device-global: allocation-free contract) ----
__device__ int    g_m[SS * BB];                   // (t_off + ideal_peak) mod L
__device__ int    g_tt[SS * BB];                  // t_off mod L
__device__ float2 g_havg[SS * BB * AA * RR];      // OCC-averaged channel, 13.4 MB

// ---- packed f32x2 helpers (sm_103a dual-lane fp32) ----
#define F2MUL(o, a, b)    asm("mul.rn.f32x2 %0, %1, %2;"      : "=l"(o) : "l"(a), "l"(b))
#define F2FMA(o, a, b, c) asm("fma.rn.f32x2 %0, %1, %2, %3;"  : "=l"(o) : "l"(a), "l"(b), "l"(c))
#define F2ADD(o, a, b)    asm("add.rn.f32x2 %0, %1, %2;"      : "=l"(o) : "l"(a), "l"(b))
#define SGNMASK 0x8000000080000000ULL

static __device__ __forceinline__ uint64_t pk2(float lo, float hi) {
    uint64_t r; asm("mov.b64 %0, {%1, %2};" : "=l"(r) : "f"(lo), "f"(hi)); return r;
}
static __device__ __forceinline__ float lo2(uint64_t v) {
    float a, b; asm("mov.b64 {%0, %1}, %2;" : "=f"(a), "=f"(b) : "l"(v)); return a;
}
static __device__ __forceinline__ float hi2(uint64_t v) {
    float a, b; asm("mov.b64 {%0, %1}, %2;" : "=f"(a), "=f"(b) : "l"(v)); return b;
}
static __device__ __forceinline__ uint64_t splat(float v) { return pk2(v, v); }

// fp32 2*pi/L, matching reference fp32 angle math
#define WF ((float)(6.283185307179586476925286766559 / 3264.0))

// fast phasor: e^{i th k}; reduce to (-pi, pi] for MUFU accuracy
static __device__ __forceinline__ float2 phasor(int k) {
    if (k > SL / 2) k -= SL;
    float s, c;
    __sincosf(WF * (float)k, &s, &c);
    return make_float2(c, s);
}

static __device__ __forceinline__ int modL(int x) { x %= SL; return x < 0 ? x + SL : x; }

// packed complex in-place multiply: (ar,ai) *= (br,bi)
#define CMUL(ar, ai, br, bi) do {            \
    uint64_t _m, _nr;                        \
    F2MUL(_m, ai, bi); _m ^= SGNMASK;        \
    F2FMA(_nr, ar, br, _m);                  \
    F2MUL(_m, ai, br);                       \
    F2FMA(ai, ar, bi, _m);                   \
    ar = _nr;                                \
} while (0)

// ---- mbarrier / TMA-bulk helpers ----
static __device__ __forceinline__ uint32_t smem_u32(const void* p) {
    uint32_t r;
    asm("{ .reg .u64 t; cvta.to.shared.u64 t, %1; cvt.u32.u64 %0, t; }" : "=r"(r) : "l"(p));
    return r;
}
#define MBAR_INIT(addr, cnt) \
    asm volatile("mbarrier.init.shared.b64 [%0], %1;" :: "r"(addr), "r"(cnt) : "memory")
#define MBAR_EXPECT_TX(addr, bytes) \
    asm volatile("mbarrier.arrive.expect_tx.shared.b64 _, [%0], %1;" :: "r"(addr), "r"(bytes) : "memory")
#define TMA_BULK_G2S(dst, src, bytes, mbar) \
    asm volatile("cp.async.bulk.shared::cta.global.mbarrier::complete_tx::bytes [%0], [%1], %2, [%3];" \
        :: "r"(dst), "l"(src), "r"(bytes), "r"(mbar) : "memory")
static __device__ __forceinline__ void mbar_wait0(uint32_t addr) {
    asm volatile(
        "{\n\t"
        ".reg .pred P;\n\t"
        "WAIT_%=:\n\t"
        "mbarrier.try_wait.parity.acquire.cta.shared::cta.b64 P, [%0], 0, 0x989680;\n\t"
        "@P bra.uni DONE_%=;\n\t"
        "bra.uni WAIT_%=;\n\t"
        "DONE_%=:\n\t"
        "}" :: "r"(addr) : "memory");
}

// ---------------------------------------------------------------------------
// Chebyshev accumulation chunk for one class: given W (FFT4 output), seed s,
// phi = e^{i 4 th p}, tc = 2 Re(phi): acc_j += (+-) W*s*phi^j  (3-term chain,
// alternating-sign substitution; signs consistent per j; only |acc|^2 used).
// ---------------------------------------------------------------------------
template <int S>
static __device__ __forceinline__ void eval_cheb(
    uint64_t Wr, uint64_t Wi, uint64_t sr, uint64_t si,
    uint64_t phir, uint64_t phii, uint64_t tc, uint64_t ntc,
    uint64_t* accr, uint64_t* acci)
{
    uint64_t m, v0r, v0i;
    F2MUL(m, Wi, si); m ^= SGNMASK;
    F2FMA(v0r, Wr, sr, m);
    F2MUL(m, Wi, sr);
    F2FMA(v0i, Wr, si, m);
    F2ADD(accr[0], accr[0], v0r);
    F2ADD(acci[0], acci[0], v0i);

    uint64_t v1r, v1i;
    F2MUL(m, v0i, phii); m ^= SGNMASK;
    F2FMA(v1r, v0r, phir, m);
    F2MUL(m, v0i, phir);
    F2FMA(v1i, v0r, phii, m);
    F2ADD(accr[1], accr[1], v1r);
    F2ADD(acci[1], acci[1], v1i);

    uint64_t pr = v0r, pi_ = v0i, cr = v1r, ci_ = v1i;
#pragma unroll
    for (int j = 2; j < S; j++) {
        uint64_t co = (j & 1) ? tc : ntc;
        uint64_t nr, ni;
        F2FMA(nr, co, cr, pr);
        F2FMA(ni, co, ci_, pi_);
        pr = cr; pi_ = ci_; cr = nr; ci_ = ni;
        F2ADD(accr[j], accr[j], nr);
        F2ADD(acci[j], acci[j], ni);
    }
}

// warp-reduce packed complex, lane0 writes |X|^2
template <int S>
static __device__ __forceinline__ void reduce_pows(
    float* powdst /*stride-4*/, const uint64_t* accr, const uint64_t* acci, int lane)
{
#pragma unroll
    for (int j = 0; j < S; j++) {
        float rr = lo2(accr[j]) + hi2(accr[j]);
        float ii = lo2(acci[j]) + hi2(acci[j]);
#pragma unroll
        for (int o = 16; o > 0; o >>= 1) {
            rr += __shfl_xor_sync(0xFFFFFFFFu, rr, o);
            ii += __shfl_xor_sync(0xFFFFFFFFu, ii, o);
        }
        if (lane == 0) powdst[4 * j] = rr * rr + ii * ii;
    }
}

// ---------------------------------------------------------------------------
// Two residue classes per warp (sharing data loads + FFT4 halves).
//   PARITY 0: class0 (S=5, dmin=-8, slot+2) and class2 (S=6, dmin=-10, slot+0)
//   PARITY 1: class1 (S=5, dmin=-7, slot+3) and class3 (S=5, dmin=-9, slot+1)
// ---------------------------------------------------------------------------
template <int PARITY>
static __device__ __forceinline__ void do_class2(
    const float* br, const float* bi,   // smem, 3264 floats each
    int n0, int lane, float* powrow)
{
    constexpr int SA   = 5;
    constexpr int SB   = (PARITY == 0) ? 6 : 5;
    constexpr int DMA  = (PARITY == 0) ? -8  : -7;
    constexpr int DMB  = (PARITY == 0) ? -10 : -9;
    constexpr int OFFA = DMA + 10;   // 2 or 3
    constexpr int OFFB = DMB + 10;   // 0 or 1

    const int p0 = 2 * lane;     // packed pair (p0, p0+1); stride 64/iter
    const int fA = n0 + DMA;
    const int fB = n0 + DMB;

    float2 ea = phasor(modL(fA * p0)), eb = phasor(modL(fA * (p0 + 1)));
    uint64_t sAr = pk2(ea.x, eb.x), sAi = pk2(ea.y, eb.y);
    ea = phasor(modL(fB * p0)); eb = phasor(modL(fB * (p0 + 1)));
    uint64_t sBr = pk2(ea.x, eb.x), sBi = pk2(ea.y, eb.y);

    float2 st = phasor(modL(fA * 64));
    uint64_t stAr = splat(st.x), stAi = splat(st.y);
    st = phasor(modL(fB * 64));
    uint64_t stBr = splat(st.x), stBi = splat(st.y);

    float2 pa = phasor(4 * p0), pb = phasor(4 * p0 + 4);
    uint64_t phir = pk2(pa.x, pb.x), phii = pk2(pa.y, pb.y);
    float2 psc = phasor(256);
    uint64_t pstr = splat(psc.x), psti = splat(psc.y);

    uint64_t aAr[SA], aAi[SA], aBr[SB], aBi[SB];
#pragma unroll
    for (int j = 0; j < SA; j++) { aAr[j] = aAi[j] = 0ULL; }
#pragma unroll
    for (int j = 0; j < SB; j++) { aBr[j] = aBi[j] = 0ULL; }

    int p = p0;
#pragma unroll 1
    for (int it = 0; it < 13; ++it, p += 64) {
        const bool v = (p < PDIM);
        uint64_t xr0 = v ? *(const uint64_t*)(br + p)            : 0ULL;
        uint64_t xr1 = v ? *(const uint64_t*)(br + p + PDIM)     : 0ULL;
        uint64_t xr2 = v ? *(const uint64_t*)(br + p + 2 * PDIM) : 0ULL;
        uint64_t xr3 = v ? *(const uint64_t*)(br + p + 3 * PDIM) : 0ULL;
        uint64_t xi0 = v ? *(const uint64_t*)(bi + p)            : 0ULL;
        uint64_t xi1 = v ? *(const uint64_t*)(bi + p + PDIM)     : 0ULL;
        uint64_t xi2 = v ? *(const uint64_t*)(bi + p + 2 * PDIM) : 0ULL;
        uint64_t xi3 = v ? *(const uint64_t*)(bi + p + 3 * PDIM) : 0ULL;

        uint64_t WAr, WAi, WBr, WBi;
        if (PARITY == 0) {
            // even FFT4 outputs: t0 = z0+z2, t2 = z1+z3; W0 = t0+t2, W2 = t0-t2
            uint64_t t0r, t0i, t2r, t2i;
            F2ADD(t0r, xr0, xr2); F2ADD(t0i, xi0, xi2);
            F2ADD(t2r, xr1, xr3); F2ADD(t2i, xi1, xi3);
            F2ADD(WAr, t0r, t2r); F2ADD(WAi, t0i, t2i);
            uint64_t n1 = t2r ^ SGNMASK, n2 = t2i ^ SGNMASK;
            F2ADD(WBr, t0r, n1);  F2ADD(WBi, t0i, n2);
        } else {
            // odd: t1 = z0-z2, t3 = z1-z3; W1 = t1 + i t3, W3 = t1 - i t3
            uint64_t nr2 = xr2 ^ SGNMASK, ni2 = xi2 ^ SGNMASK;
            uint64_t nr3 = xr3 ^ SGNMASK, ni3 = xi3 ^ SGNMASK;
            uint64_t t1r, t1i, t3r, t3i;
            F2ADD(t1r, xr0, nr2); F2ADD(t1i, xi0, ni2);
            F2ADD(t3r, xr1, nr3); F2ADD(t3i, xi1, ni3);
            uint64_t nt3i = t3i ^ SGNMASK, nt3r = t3r ^ SGNMASK;
            F2ADD(WAr, t1r, nt3i); F2ADD(WAi, t1i, t3r);
            F2ADD(WBr, t1r, t3i);  F2ADD(WBi, t1i, nt3r);
        }

        uint64_t tc, ntc;
        F2ADD(tc, phir, phir);
        ntc = tc ^ SGNMASK;

        eval_cheb<SA>(WAr, WAi, sAr, sAi, phir, phii, tc, ntc, aAr, aAi);
        eval_cheb<SB>(WBr, WBi, sBr, sBi, phir, phii, tc, ntc, aBr, aBi);

        CMUL(sAr, sAi, stAr, stAi);
        CMUL(sBr, sBi, stBr, stBi);
        CMUL(phir, phii, pstr, psti);
    }

    reduce_pows<SA>(powrow + OFFA, aAr, aAi, lane);
    reduce_pows<SB>(powrow + OFFB, aBr, aBi, lane);
}

// ---------------------------------------------------------------------------
// k_main: TMA-bulk the whole (s,b) slice into smem, then phase A (timing
//   search, 2 classes/warp) + argmax + phase B (OCC avg), all smem-fed.
//   One block per (s,b); 256 threads = 8 warps: warp w -> antenna w>>1,
//   parity w&1.
// ---------------------------------------------------------------------------
__global__ void __launch_bounds__(256)
k_main(const float* __restrict__ lsr, const float* __restrict__ lsi,
       const int* __restrict__ cs) {
    extern __shared__ float smbuf[];          // [(a*2+c) * SL], 104448 B
    __shared__ uint64_t mbar[AA];
    __shared__ float    spow[AA][NOFF];
    __shared__ float    shpow[NOFF];
    __shared__ int      sh_mm;

    const int sb   = blockIdx.x;
    const int s    = sb / BB;
    const int w    = threadIdx.x >> 5;
    const int lane = threadIdx.x & 31;

    const int ideal = ((KK - cs[s]) % KK) * LPK;   // in [0,SL), multiple of 4

    if (threadIdx.x == 0) {
#pragma unroll
        for (int a = 0; a < AA; a++) MBAR_INIT(smem_u32(&mbar[a]), 1);
    }
    __syncthreads();
    if (threadIdx.x == 0) {
#pragma unroll
        for (int a = 0; a < AA; a++) {
            uint32_t mb = smem_u32(&mbar[a]);
            MBAR_EXPECT_TX(mb, 2 * SL * 4);
            const float* srcr = lsr + ((size_t)sb * AA + a) * SL;
            const float* srci = lsi + ((size_t)sb * AA + a) * SL;
            TMA_BULK_G2S(smem_u32(smbuf + (a * 2) * SL),     srcr, SL * 4, mb);
            TMA_BULK_G2S(smem_u32(smbuf + (a * 2 + 1) * SL), srci, SL * 4, mb);
        }
    }

    // ---- phase A: one double-class job per warp ----
    const int a      = w >> 1;
    const int parity = w & 1;
    mbar_wait0(smem_u32(&mbar[a]));
    {
        const float* br = smbuf + (a * 2) * SL;
        const float* bi = smbuf + (a * 2 + 1) * SL;
        if (parity == 0) do_class2<0>(br, bi, ideal, lane, &spow[a][0]);
        else             do_class2<1>(br, bi, ideal, lane, &spow[a][0]);
    }
    __syncthreads();

    // ---- argmax over candidates (first-max tie rule) ----
    if (threadIdx.x < NOFF) {
        int d = threadIdx.x;
        shpow[d] = spow[0][d] + spow[1][d] + spow[2][d] + spow[3][d];
    }
    __syncthreads();
    if (threadIdx.x == 0) {
        int   best = 0;
        float bp   = shpow[0];
        for (int j = 1; j < NOFF; j++)
            if (shpow[j] > bp) { bp = shpow[j]; best = j; }
        int toff = best - 10;
        int mmv  = modL(toff + ideal);
        g_m[sb]  = mmv;
        g_tt[sb] = modL(toff);
        sh_mm    = mmv;
    }
    __syncthreads();

    // ---- phase B: OCC averaging from SMEM ----
    const int mmv = sh_mm;
    float2 msv = phasor(mmv);                        // e^{i th mm}
    float2 spv = phasor((mmv * 1024) % SL);          // r += 256 step
    float2 sd0 = phasor((mmv * 4 * (int)threadIdx.x) % SL);

#pragma unroll
    for (int aa = 0; aa < AA; aa++) {
        const float* br2 = smbuf + (aa * 2) * SL;
        const float* bi2 = smbuf + (aa * 2 + 1) * SL;
        float2* ho = g_havg + ((size_t)sb * AA + aa) * RR;
        float pc = sd0.x, ps = sd0.y;
        for (int r = threadIdx.x; r < RR; r += 256) {
            int l0 = 4 * r;
            float4 xr = *(const float4*)(br2 + l0);
            float4 xi = *(const float4*)(bi2 + l0);
            float xrv[4] = {xr.x, xr.y, xr.z, xr.w};
            float xiv[4] = {xi.x, xi.y, xi.z, xi.w};
            float qc = pc, qs = ps;
            float sr = 0.0f, si = 0.0f;
#pragma unroll
            for (int j = 0; j < 4; j++) {
                sr += xrv[j] * qc - xiv[j] * qs;
                si += xrv[j] * qs + xiv[j] * qc;
                if (j < 3) {
                    float nc = qc * msv.x - qs * msv.y;
                    float ns = qc * msv.y + qs * msv.x;
                    qc = nc; qs = ns;
                }
            }
            ho[r] = make_float2(sr * 0.25f, si * 0.25f);
            float nc = pc * spv.x - ps * spv.y;
            float ns = pc * spv.y + ps * spv.x;
            pc = nc; ps = ns;
        }
    }
}

// ---------------------------------------------------------------------------
// k_final: warp-per-stream over a 128-l tile for one (b,a); 4 l's per thread.
// ---------------------------------------------------------------------------
__global__ void __launch_bounds__(256)
k_final(const float* __restrict__ lsr, const float* __restrict__ lsi,
        float* __restrict__ out) {
    const int blk  = blockIdx.x;
    const int ba   = blk / NTILE;
    const int tile = blk % NTILE;
    const int a    = ba % AA;
    const int b    = ba / AA;
    const int s    = threadIdx.x >> 5;   // warp = stream
    const int lane = threadIdx.x & 31;

    const int lbase = tile * TILE;
    const int l0    = lbase + lane * 4;
    const bool act  = (l0 < SL);

    __shared__ float shc[SS][2 * TILE];   // recon contributions
    __shared__ float shres[2 * TILE];     // residual

    const int sb = s * BB + b;
    const int mm = g_m[sb];
    const int tt = g_tt[sb];
    const float2* hv = g_havg + ((size_t)sb * AA + a) * RR;

    float hr[4], hi[4], pr[4], pi[4];

    if (act) {
        int g = l0 >> 2;
        float2 hm = hv[max(g - 1, 0)];
        float2 h0 = hv[g];
        float2 hp = hv[min(g + 1, RR - 1)];

        float f0 = (g > 0)      ? 0.625f : 0.0f;
        float f1 = (g > 0)      ? 0.875f : 0.0f;
        float f2 = (g < RR - 1) ? 0.125f : 0.0f;
        float f3 = (g < RR - 1) ? 0.375f : 0.0f;

        hr[0] = hm.x * (1.0f - f0) + h0.x * f0;  hi[0] = hm.y * (1.0f - f0) + h0.y * f0;
        hr[1] = hm.x * (1.0f - f1) + h0.x * f1;  hi[1] = hm.y * (1.0f - f1) + h0.y * f1;
        hr[2] = h0.x * (1.0f - f2) + hp.x * f2;  hi[2] = h0.y * (1.0f - f2) + hp.y * f2;
        hr[3] = h0.x * (1.0f - f3) + hp.x * f3;  hi[3] = h0.y * (1.0f - f3) + hp.y * f3;

        // mm*l0 <= 3263*3263 ~ 10.6M: int32-safe
        float2 pm = phasor((mm * l0) % SL);
        float2 ms = phasor(mm);
        float pmc = pm.x, pms = pm.y;

        float cr[4], cc[4];
#pragma unroll
        for (int j = 0; j < 4; j++) {
            pr[j] = pmc; pi[j] = pms;
            cr[j] = hr[j] * pmc + hi[j] * pms;   // h_interp * conj(ph_m)
            cc[j] = hi[j] * pmc - hr[j] * pms;
            if (j < 3) {
                float nc = pmc * ms.x - pms * ms.y;
                float ns = pmc * ms.y + pms * ms.x;
                pmc = nc; pms = ns;
            }
        }
        float4* dst = (float4*)&shc[s][lane * 8];
        dst[0] = make_float4(cr[0], cc[0], cr[1], cc[1]);
        dst[1] = make_float4(cr[2], cc[2], cr[3], cc[3]);
    }
    __syncthreads();

    // residual reduction
    {
        int ll   = threadIdx.x >> 1;
        int comp = threadIdx.x & 1;
        int lg   = lbase + ll;
        if (lg < SL) {
            float sum = 0.0f;
#pragma unroll
            for (int ss2 = 0; ss2 < SS; ss2++) sum += shc[ss2][ll * 2 + comp];
            const float* ls0 = comp ? lsi : lsr;
            shres[ll * 2 + comp] = ls0[(size_t)ba * SL + lg] - sum;
        }
    }
    __syncthreads();

    if (act) {
        float2 pt = phasor((tt * l0) % SL);
        float2 ts = phasor(tt);
        float ptc = pt.x, pts = pt.y;

        float4 r01 = *(float4*)&shres[lane * 8];
        float4 r23 = *(float4*)&shres[lane * 8 + 4];
        float rres[4] = {r01.x, r01.z, r23.x, r23.z};
        float rims[4] = {r01.y, r01.w, r23.y, r23.w};

        float4 outr, outi;
        float* orp = &outr.x;
        float* oip = &outi.x;
#pragma unroll
        for (int j = 0; j < 4; j++) {
            float wr = hr[j] + rres[j] * pr[j] - rims[j] * pi[j];
            float wi = hi[j] + rres[j] * pi[j] + rims[j] * pr[j];
            orp[j] = wr * ptc + wi * pts;
            oip[j] = wi * ptc - wr * pts;
            if (j < 3) {
                float nc = ptc * ts.x - pts * ts.y;
                float ns = ptc * ts.y + pts * ts.x;
                ptc = nc; pts = ns;
            }
        }

        const size_t TOT = (size_t)SS * BB * AA * SL;
        size_t off = ((size_t)sb * AA + a) * SL + (size_t)l0;
        *(float4*)(out + off)       = outr;
        *(float4*)(out + TOT + off) = outi;
    }
}

// ---------------------------------------------------------------------------
extern "C" void kernel_launch(void* const* d_in, const int* in_sizes, int n_in,
                              void* d_out, int out_size) {
    (void)in_sizes; (void)n_in; (void)out_size;
    const float* lsr = (const float*)d_in[0];
    const float* lsi = (const float*)d_in[1];
    const int*   cs  = (const int*)d_in[2];
    float*       out = (float*)d_out;

    cudaFuncSetAttribute(k_main, cudaFuncAttributeMaxDynamicSharedMemorySize, SMEM_DYN);

    k_main<<<SS * BB, 256, SMEM_DYN>>>(lsr, lsi, cs);
    k_final<<<BB * AA * NTILE, 256>>>(lsr, lsi, out);
}